// round 4
// baseline (speedup 1.0000x reference)
#include <cuda_runtime.h>

// Problem constants (fixed by the reference)
#define BB 8
#define NT 256
#define WHD 21
#define PP 441          // WHD*WHD
#define SPITCH 23       // padded patch pitch
#define SPSZ (SPITCH * 23 + 8)   // +8 zero slack for row-chunk over-read at c==5
#define IMH 1024
#define IMW 1024
#define ITERS 20
#define NTHREADS 128
#define NWARPS 4

__global__ __launch_bounds__(NTHREADS, 14)
void mt_kernel(const float* __restrict__ track,
               const float* __restrict__ imgs,
               float* __restrict__ out)
{
    const int id = blockIdx.x;           // 0 .. B*NT-1
    const int b = id >> 8;               // id / NT (NT = 256)
    const int t = id & 255;

    const float* f0 = imgs + (size_t)b * 2 * IMH * IMW;   // frame 0
    const float* f1 = f0 + (size_t)(IMH * IMW);           // frame 1

    __shared__ float  sP[SPSZ];          // zero-padded sampled patch
    __shared__ float  sSec[PP];          // 'second' patch (frame 1 at init pos)
    __shared__ float4 sXW[WHD];          // per-j: (x1-x, x-x0, bits(xi0), bits(xi1))
    __shared__ float4 sYW[WHD];          // per-i: (y1-y, y-y0, bits(yi0*1024), bits(yi1*1024))
    __shared__ float  sRed[5][NWARPS];   // per-warp partial sums

    const int tid  = threadIdx.x;
    const int lane = tid & 31;
    const int wid  = tid >> 5;

    // per-thread shift state (all threads compute identically)
    float sx, sy;
    {
        const float SCALE = 21.0f / 1024.0f;   // exact in fp32
        sx = track[b * (NT * 2) + t * 2 + 0] / SCALE;
        sy = track[b * (NT * 2) + t * 2 + 1] / SCALE;
    }

    // zero padded patch (+slack); border & slack stay zero forever
    #pragma unroll
    for (int k = tid; k < SPSZ; k += NTHREADS) sP[k] = 0.0f;

    // weight/index tables: exact replication of reference clip-then-weight bilinear
    auto writeTables = [&](float ssx, float ssy) {
        if (tid < WHD) {
            float g  = -1.0f + 0.1f * (float)tid;
            float x  = (g + ssx) * 10.5f;        // WH*0.5
            float fx = floorf(x);
            float x0 = fminf(fmaxf(fx,        0.0f), 1023.0f);
            float x1 = fminf(fmaxf(fx + 1.0f, 0.0f), 1023.0f);
            sXW[tid] = make_float4(x1 - x, x - x0,
                                   __int_as_float((int)x0),
                                   __int_as_float((int)x1));
        } else if (tid >= 32 && tid < 32 + WHD) {
            int   i  = tid - 32;
            float g  = -1.0f + 0.1f * (float)i;
            float y  = (g + ssy) * 10.5f;
            float fy = floorf(y);
            float y0 = fminf(fmaxf(fy,        0.0f), 1023.0f);
            float y1 = fminf(fmaxf(fy + 1.0f, 0.0f), 1023.0f);
            sYW[i] = make_float4(y1 - y, y - y0,
                                 __int_as_float(((int)y0) * IMW),
                                 __int_as_float(((int)y1) * IMW));
        }
    };

    // sample one point from tables (reference multiply ordering preserved)
    auto sample = [&](const float* __restrict__ f, int i, int j) -> float {
        float4 xw = sXW[j];
        float4 yw = sYW[i];
        int y0m = __float_as_int(yw.z), y1m = __float_as_int(yw.w);
        int x0i = __float_as_int(xw.z), x1i = __float_as_int(xw.w);
        float wa = yw.x * xw.x;
        float wb = yw.x * xw.y;
        float wc = yw.y * xw.x;
        float wd = yw.y * xw.y;
        return wa * __ldg(f + (y0m + x0i)) + wb * __ldg(f + (y0m + x1i))
             + wc * __ldg(f + (y1m + x0i)) + wd * __ldg(f + (y1m + x1i));
    };

    writeTables(sx, sy);
    __syncthreads();

    // 'second' (frame 1 at initial positions) — fixed for all iterations
    {
        int i = tid / WHD;
        int j = tid - i * WHD;
        float* o1 = out + ((((size_t)b * 2) + 1) * NT + t) * PP;
        #pragma unroll
        for (int k = 0; k < 4; ++k) {
            if (i < WHD) {
                float s = sample(f1, i, j);
                int p = tid + k * NTHREADS;
                sSec[p] = s;
                o1[p]   = s;
            }
            j += 2; i += 6; if (j >= WHD) { j -= WHD; ++i; }   // p += 128
        }
    }

    // stencil mapping: thread = (row si, 4-col chunk sc), 126 active threads
    const int si  = tid / 6;
    const int sc  = tid - si * 6;
    const int sj0 = sc * 4;
    const int sncols = (sc == 5) ? 1 : 4;

    for (int it = 0; it < ITERS; ++it) {
        // ---- sample f0 into padded patch (p-layout, coalesced gathers) ----
        {
            int i = tid / WHD;
            int j = tid - i * WHD;
            #pragma unroll
            for (int k = 0; k < 4; ++k) {
                if (i < WHD) {
                    sP[(i + 1) * SPITCH + (j + 1)] = sample(f0, i, j);
                }
                j += 2; i += 6; if (j >= WHD) { j -= WHD; ++i; }
            }
        }
        __syncthreads();                       // sync A: patch (and sSec/tables) visible

        // ---- row-chunk Sobel stencil + local accumulation ----
        float v0 = 0.f, v1 = 0.f, v2 = 0.f, v3 = 0.f, v4 = 0.f;
        if (si < WHD) {
            float e[6], d[6], cen[4];
            const int base = si * SPITCH + sj0;
            #pragma unroll
            for (int cc = 0; cc < 6; ++cc) {
                float la = sP[base + cc];
                float lb = sP[base + SPITCH + cc];
                float lc = sP[base + 2 * SPITCH + cc];
                e[cc] = fmaf(2.0f, lb, la + lc);   // r0 + 2 r1 + r2
                d[cc] = lc - la;                   // r2 - r0
                if (cc >= 1 && cc <= 4) cen[cc - 1] = lb;
            }
            #pragma unroll
            for (int jj = 0; jj < 4; ++jj) {
                if (jj < sncols) {
                    float Ix = e[jj + 2] - e[jj];
                    float Iy = fmaf(2.0f, d[jj + 1], d[jj] + d[jj + 2]);
                    float o0 = cen[jj];
                    float It = sSec[si * WHD + sj0 + jj] - o0;
                    v0 = fmaf(Ix, Ix, v0);
                    v1 = fmaf(Iy, Iy, v1);
                    v2 = fmaf(Ix, Iy, v2);
                    v3 = fmaf(Ix, It, v3);
                    v4 = fmaf(Iy, It, v4);
                }
            }
        }

        // stage 1: warp reduce
        #pragma unroll
        for (int off = 16; off; off >>= 1) {
            v0 += __shfl_down_sync(0xffffffffu, v0, off);
            v1 += __shfl_down_sync(0xffffffffu, v1, off);
            v2 += __shfl_down_sync(0xffffffffu, v2, off);
            v3 += __shfl_down_sync(0xffffffffu, v3, off);
            v4 += __shfl_down_sync(0xffffffffu, v4, off);
        }
        if (lane == 0) {
            sRed[0][wid] = v0;
            sRed[1][wid] = v1;
            sRed[2][wid] = v2;
            sRed[3][wid] = v3;
            sRed[4][wid] = v4;
        }
        __syncthreads();                       // sync B: partials visible

        // stage 2: every thread sums 4 partials and solves locally
        float Ix2  = (sRed[0][0] + sRed[0][1]) + (sRed[0][2] + sRed[0][3]);
        float Iy2  = (sRed[1][0] + sRed[1][1]) + (sRed[1][2] + sRed[1][3]);
        float IxIy = (sRed[2][0] + sRed[2][1]) + (sRed[2][2] + sRed[2][3]);
        float IxIt = (sRed[3][0] + sRed[3][1]) + (sRed[3][2] + sRed[3][3]);
        float IyIt = (sRed[4][0] + sRed[4][1]) + (sRed[4][2] + sRed[4][3]);

        float det_inv = 1.0f / (Ix2 * Iy2 - IxIy * IxIy);
        float Vx = det_inv * (Iy2    * (-IxIt) + (-IxIy) * (-IyIt));
        float Vy = det_inv * ((-IxIy) * (-IxIt) + Ix2    * (-IyIt));
        sx = sx - Vx;
        sy = sy - Vy;

        writeTables(sx, sy);
        __syncthreads();                       // sync C: new tables visible
    }

    // final sample of frame 0 at converged positions
    {
        int i = tid / WHD;
        int j = tid - i * WHD;
        float* o0p = out + ((((size_t)b * 2) + 0) * NT + t) * PP;
        #pragma unroll
        for (int k = 0; k < 4; ++k) {
            if (i < WHD) {
                o0p[tid + k * NTHREADS] = sample(f0, i, j);
            }
            j += 2; i += 6; if (j >= WHD) { j -= WHD; ++i; }
        }
    }
}

extern "C" void kernel_launch(void* const* d_in, const int* in_sizes, int n_in,
                              void* d_out, int out_size)
{
    // track_locs: 8*512 = 4096 floats; imgs: 8*2*1024*1024 floats.
    const float* track;
    const float* imgs;
    if (in_sizes[0] < in_sizes[1]) {
        track = (const float*)d_in[0];
        imgs  = (const float*)d_in[1];
    } else {
        track = (const float*)d_in[1];
        imgs  = (const float*)d_in[0];
    }
    float* out = (float*)d_out;
    mt_kernel<<<BB * NT, NTHREADS>>>(track, imgs, out);
}

// round 5
// speedup vs baseline: 1.0336x; 1.0336x over previous
#include <cuda_runtime.h>

// Problem constants (fixed by the reference)
#define BB 8
#define NT 256
#define WHD 21
#define PP 441          // WHD*WHD
#define PAD 23          // zero-padded patch dim
#define WIN 24          // staged image window dim (covers 21px span + bilinear + fp slack)
#define IMH 1024
#define IMW 1024
#define ITERS 20
#define NTHREADS 128
#define NWARPS 4
#define PTS 4           // patch points per thread (4*128 = 512 >= 441)

__global__ __launch_bounds__(NTHREADS, 14)
void mt_kernel(const float* __restrict__ track,
               const float* __restrict__ imgs,
               float* __restrict__ out)
{
    const int id = blockIdx.x;           // 0 .. B*NT-1
    const int b = id >> 8;               // id / NT (NT = 256)
    const int t = id & 255;

    const float* f0 = imgs + (size_t)b * 2 * IMH * IMW;   // frame 0
    const float* f1 = f0 + (size_t)(IMH * IMW);           // frame 1

    __shared__ float sW[WIN * WIN];      // staged f0 pixel window
    __shared__ float sP[PAD * PAD];      // zero-padded sampled patch
    __shared__ float sRed[5][NWARPS];    // per-warp partial sums

    const int tid  = threadIdx.x;
    const int lane = tid & 31;
    const int wid  = tid >> 5;

    // per-thread shift state (all threads compute identically)
    float sx, sy;
    {
        const float SCALE = 21.0f / 1024.0f;   // exact in fp32
        sx = track[b * (NT * 2) + t * 2 + 0] / SCALE;
        sy = track[b * (NT * 2) + t * 2 + 1] / SCALE;
    }

    // zero the padded patch once; border stays zero forever
    #pragma unroll
    for (int k = tid; k < PAD * PAD; k += NTHREADS) sP[k] = 0.0f;

    // direct-gather bilinear (exact reference clip-then-weight; used for the
    // once-only f1 'second' sampling and the final f0 sampling)
    auto bilinearG = [&](const float* __restrict__ f, float gx, float gy,
                         float ssx, float ssy) -> float {
        float x = (gx + ssx) * 10.5f;    // WH*0.5
        float y = (gy + ssy) * 10.5f;
        float fx = floorf(x);
        float fy = floorf(y);
        float x0 = fminf(fmaxf(fx,        0.0f), 1023.0f);
        float x1 = fminf(fmaxf(fx + 1.0f, 0.0f), 1023.0f);
        float y0 = fminf(fmaxf(fy,        0.0f), 1023.0f);
        float y1 = fminf(fmaxf(fy + 1.0f, 0.0f), 1023.0f);
        float wa = (y1 - y) * (x1 - x);
        float wb = (y1 - y) * (x  - x0);
        float wc = (y  - y0) * (x1 - x);
        float wd = (y  - y0) * (x  - x0);
        int xi0 = (int)x0, xi1 = (int)x1;
        int yi0 = (int)y0, yi1 = (int)y1;
        const float* r0 = f + yi0 * IMW;
        const float* r1 = f + yi1 * IMW;
        return wa * __ldg(r0 + xi0) + wb * __ldg(r0 + xi1)
             + wc * __ldg(r1 + xi0) + wd * __ldg(r1 + xi1);
    };

    // 'second' (frame 1 at initial positions) — fixed for all iterations
    float second[PTS];
    {
        int i = tid / WHD;
        int j = tid - i * WHD;
        float* o1 = out + ((((size_t)b * 2) + 1) * NT + t) * PP;
        #pragma unroll
        for (int k = 0; k < PTS; ++k) {
            second[k] = 0.0f;
            if (i < WHD) {
                const float gx = -1.0f + 0.1f * (float)j;
                const float gy = -1.0f + 0.1f * (float)i;
                second[k] = bilinearG(f1, gx, gy, sx, sy);
                o1[tid + k * NTHREADS] = second[k];
            }
            j += 2; i += 6; if (j >= WHD) { j -= WHD; ++i; }   // p += 128
        }
    }

    __syncthreads();   // padded border zeros visible

    for (int it = 0; it < ITERS; ++it) {
        // ---- window base (identical on every thread; monotone indices => coverage)
        // x at j=0: (-1 + sx)*10.5 ; indices over j live in [cbase, cbase+23]
        int cbase, rbase;
        {
            float xf = (-1.0f + sx) * 10.5f;
            float yf = (-1.0f + sy) * 10.5f;
            cbase = min(max((int)floorf(xf), 0), IMW - WIN);
            rbase = min(max((int)floorf(yf), 0), IMH - WIN);
        }

        // ---- stage the 24x24 f0 window (coalesced) ----
        {
            const float* wsrc = f0 + rbase * IMW + cbase;
            #pragma unroll
            for (int k = 0; k < 5; ++k) {
                int idx = tid + k * NTHREADS;
                if (idx < WIN * WIN) {
                    int r = idx / WIN;
                    int c = idx - r * WIN;
                    sW[idx] = __ldg(wsrc + r * IMW + c);
                }
            }
        }
        __syncthreads();                       // sync W: window visible

        // ---- sample f0 from the SMEM window into the padded patch ----
        float o0[PTS];
        {
            int i = tid / WHD;
            int j = tid - i * WHD;
            #pragma unroll
            for (int k = 0; k < PTS; ++k) {
                if (i < WHD) {
                    const float gx = -1.0f + 0.1f * (float)j;
                    const float gy = -1.0f + 0.1f * (float)i;
                    float x = (gx + sx) * 10.5f;
                    float y = (gy + sy) * 10.5f;
                    float fx = floorf(x);
                    float fy = floorf(y);
                    float x0 = fminf(fmaxf(fx,        0.0f), 1023.0f);
                    float x1 = fminf(fmaxf(fx + 1.0f, 0.0f), 1023.0f);
                    float y0 = fminf(fmaxf(fy,        0.0f), 1023.0f);
                    float y1 = fminf(fmaxf(fy + 1.0f, 0.0f), 1023.0f);
                    float wa = (y1 - y) * (x1 - x);
                    float wb = (y1 - y) * (x  - x0);
                    float wc = (y  - y0) * (x1 - x);
                    float wd = (y  - y0) * (x  - x0);
                    int xi0 = (int)x0 - cbase, xi1 = (int)x1 - cbase;
                    int yi0 = (int)y0 - rbase, yi1 = (int)y1 - rbase;
                    const float* w0 = sW + yi0 * WIN;
                    const float* w1 = sW + yi1 * WIN;
                    o0[k] = wa * w0[xi0] + wb * w0[xi1]
                          + wc * w1[xi0] + wd * w1[xi1];
                    sP[(i + 1) * PAD + (j + 1)] = o0[k];
                }
                j += 2; i += 6; if (j >= WHD) { j -= WHD; ++i; }
            }
        }
        __syncthreads();                       // sync A: patch visible

        // ---- per-point zero-padded Sobel stencil + local accumulation ----
        float v0 = 0.f, v1 = 0.f, v2 = 0.f, v3 = 0.f, v4 = 0.f;
        {
            int i = tid / WHD;
            int j = tid - i * WHD;
            #pragma unroll
            for (int k = 0; k < PTS; ++k) {
                if (i < WHD) {
                    const int pb = (i + 1) * PAD + (j + 1);
                    float a00 = sP[pb - PAD - 1], a01 = sP[pb - PAD], a02 = sP[pb - PAD + 1];
                    float a10 = sP[pb - 1],                            a12 = sP[pb + 1];
                    float a20 = sP[pb + PAD - 1], a21 = sP[pb + PAD], a22 = sP[pb + PAD + 1];
                    float Ix = (a02 - a00) + 2.0f * (a12 - a10) + (a22 - a20);
                    float Iy = (a20 - a00) + 2.0f * (a21 - a01) + (a22 - a02);
                    float It = second[k] - o0[k];
                    v0 = fmaf(Ix, Ix, v0);
                    v1 = fmaf(Iy, Iy, v1);
                    v2 = fmaf(Ix, Iy, v2);
                    v3 = fmaf(Ix, It, v3);
                    v4 = fmaf(Iy, It, v4);
                }
                j += 2; i += 6; if (j >= WHD) { j -= WHD; ++i; }
            }
        }

        // stage 1: warp reduce
        #pragma unroll
        for (int off = 16; off; off >>= 1) {
            v0 += __shfl_down_sync(0xffffffffu, v0, off);
            v1 += __shfl_down_sync(0xffffffffu, v1, off);
            v2 += __shfl_down_sync(0xffffffffu, v2, off);
            v3 += __shfl_down_sync(0xffffffffu, v3, off);
            v4 += __shfl_down_sync(0xffffffffu, v4, off);
        }
        if (lane == 0) {
            sRed[0][wid] = v0;
            sRed[1][wid] = v1;
            sRed[2][wid] = v2;
            sRed[3][wid] = v3;
            sRed[4][wid] = v4;
        }
        __syncthreads();                       // sync B: partials visible

        // stage 2: every thread sums 4 partials and solves locally
        float Ix2  = (sRed[0][0] + sRed[0][1]) + (sRed[0][2] + sRed[0][3]);
        float Iy2  = (sRed[1][0] + sRed[1][1]) + (sRed[1][2] + sRed[1][3]);
        float IxIy = (sRed[2][0] + sRed[2][1]) + (sRed[2][2] + sRed[2][3]);
        float IxIt = (sRed[3][0] + sRed[3][1]) + (sRed[3][2] + sRed[3][3]);
        float IyIt = (sRed[4][0] + sRed[4][1]) + (sRed[4][2] + sRed[4][3]);

        float det_inv = 1.0f / (Ix2 * Iy2 - IxIy * IxIy);
        float Vx = det_inv * (Iy2    * (-IxIt) + (-IxIy) * (-IyIt));
        float Vy = det_inv * ((-IxIy) * (-IxIt) + Ix2    * (-IyIt));
        sx = sx - Vx;
        sy = sy - Vy;
    }

    // final sample of frame 0 at converged positions (once; direct gathers)
    {
        int i = tid / WHD;
        int j = tid - i * WHD;
        float* o0p = out + ((((size_t)b * 2) + 0) * NT + t) * PP;
        #pragma unroll
        for (int k = 0; k < PTS; ++k) {
            if (i < WHD) {
                const float gx = -1.0f + 0.1f * (float)j;
                const float gy = -1.0f + 0.1f * (float)i;
                o0p[tid + k * NTHREADS] = bilinearG(f0, gx, gy, sx, sy);
            }
            j += 2; i += 6; if (j >= WHD) { j -= WHD; ++i; }
        }
    }
}

extern "C" void kernel_launch(void* const* d_in, const int* in_sizes, int n_in,
                              void* d_out, int out_size)
{
    // track_locs: 8*512 = 4096 floats; imgs: 8*2*1024*1024 floats.
    const float* track;
    const float* imgs;
    if (in_sizes[0] < in_sizes[1]) {
        track = (const float*)d_in[0];
        imgs  = (const float*)d_in[1];
    } else {
        track = (const float*)d_in[1];
        imgs  = (const float*)d_in[0];
    }
    float* out = (float*)d_out;
    mt_kernel<<<BB * NT, NTHREADS>>>(track, imgs, out);
}